// round 4
// baseline (speedup 1.0000x reference)
#include <cuda_runtime.h>
#include <cuda_bf16.h>

// Problem constants (fixed by the dataset)
#define B_  8
#define S_  4096
#define D_  1024
#define H_  16
#define HD_ 64
#define NR_ 32
#define ROWS_ (B_ * S_ * H_)        // 524288
#define RPB 128                      // rows per block
#define PITCH 69                     // row pitch in words; bank multiplier 5 (odd)

// per-row-class pad inserted before columns >= 32: b[p] for p = r & 3
// b = {3,1,2,2}  (nibble-packed). Makes stage-in, Givens, stage-out all
// bank-conflict-free simultaneously (verified mod-32 algebra).
__device__ __forceinline__ int bpad(int p) { return (0x2213 >> (p * 4)) & 0xF; }

// ---------------------------------------------------------------------------
// Single fused kernel: per-block param prep + Givens chain + RoPE remix.
// ---------------------------------------------------------------------------
__global__ __launch_bounds__(RPB, 6)
void rotary_fused_kernel(const float* __restrict__ x,
                         const float* __restrict__ thetas,
                         const float* __restrict__ r_pairs,
                         const float* __restrict__ theta_scale,
                         const float* __restrict__ inv_freq,
                         const float* __restrict__ r_matrix,
                         float* __restrict__ out) {
    __shared__ float sm[RPB * PITCH];
    __shared__ __align__(16) float s_cos[8 * NR_];   // 8 s-positions x 32 freqs
    __shared__ __align__(16) float s_sin[8 * NR_];
    __shared__ float sc[NR_], ss[NR_];
    __shared__ int   spack[NR_];                      // i | (j<<8)

    const int t = threadIdx.x;
    const long long block_row0 = (long long)blockIdx.x * RPB;
    const float4* __restrict__ x4 = (const float4*)(x + block_row0 * HD_);
    float4* __restrict__ o4 = (float4*)(out + block_row0 * HD_);

    // ---- stage-in: 128x64 floats, coalesced float4 LDG -> padded smem
    {
        const int c0 = (t & 15) * 4;
        const int p  = (t >> 4) & 3;                 // row class, constant per thread
        const int w0 = c0 + ((c0 >= 32) ? bpad(p) : 0);
        const int r0 = t >> 4;
        #pragma unroll
        for (int it = 0; it < 16; it++) {
            float4 v = x4[t + it * RPB];
            float* pz = &sm[(r0 + 8 * it) * PITCH + w0];
            pz[0] = v.x; pz[1] = v.y; pz[2] = v.z; pz[3] = v.w;
        }
    }

    // ---- per-block rotation params (threads 0..31)
    if (t < NR_) {
        float th = thetas[t] * theta_scale[0];
        float sv, cv;
        sincosf(th, &sv, &cv);
        sc[t] = cv;
        ss[t] = sv;
        int i = (int)r_pairs[2 * t];
        int j = (int)r_pairs[2 * t + 1];
        if (i < 0) i = 0; if (i > HD_ - 1) i = HD_ - 1;
        if (j < 0) j = 0; if (j > HD_ - 1) j = HD_ - 1;
        spack[t] = i | (j << 8);
    }

    // ---- per-block RoPE table slice: 8 consecutive s-positions (rows/16)
    {
        int s0 = (int)((block_row0 >> 4) & (S_ - 1));
        #pragma unroll
        for (int u = 0; u < 2; u++) {
            int idx = t + u * RPB;          // 0..255
            int g = idx >> 5;
            int k = idx & (NR_ - 1);
            float a = (float)(s0 + g) * inv_freq[k];
            float sv, cv;
            sincosf(a, &sv, &cv);
            s_cos[idx] = cv;
            s_sin[idx] = sv;
        }
    }

    // ---- per-block identity check on r_matrix (coalesced float4, 8/thread)
    int ok = 1;
    {
        const float4* rm4 = (const float4*)r_matrix;
        #pragma unroll
        for (int k = 0; k < 8; k++) {
            int q = k * RPB + t;            // float4 idx in [0,1024)
            float4 v = rm4[q];
            int e = q * 4;
            ok &= (v.x == (((e + 0) >> 6) == ((e + 0) & 63) ? 1.0f : 0.0f));
            ok &= (v.y == (((e + 1) >> 6) == ((e + 1) & 63) ? 1.0f : 0.0f));
            ok &= (v.z == (((e + 2) >> 6) == ((e + 2) & 63) ? 1.0f : 0.0f));
            ok &= (v.w == (((e + 3) >> 6) == ((e + 3) & 63) ? 1.0f : 0.0f));
        }
    }
    const int identity = __syncthreads_and(ok);   // barrier + block-wide AND

    // ---- per-row sequential Givens rotations (thread t owns row t)
    {
        const int bp = bpad(t & 3);
        float* row = &sm[t * PITCH];
        #pragma unroll
        for (int k = 0; k < NR_; k++) {
            int pk = spack[k];
            int i = pk & 0xFF, j = pk >> 8;
            float c = sc[k], s = ss[k];
            int oi = i + ((i >= 32) ? bp : 0);
            int oj = j + ((j >= 32) ? bp : 0);
            float xi = row[oi];
            float xj = row[oj];
            if (i == j) {
                row[oi] = xi * c;
            } else {
                row[oi] = xi * c + xj * s;
                row[oj] = xj * c - xi * s;
            }
        }

        // general path: dense multiply by r_matrix (not taken when r_matrix == I)
        if (!identity) {
            float y[HD_];
            for (int c2 = 0; c2 < HD_; c2++) {
                float acc = 0.0f;
                for (int k = 0; k < HD_; k++) {
                    int ok2 = k + ((k >= 32) ? bp : 0);
                    acc = fmaf(row[ok2], __ldg(&r_matrix[k * HD_ + c2]), acc);
                }
                y[c2] = acc;
            }
            for (int c2 = 0; c2 < HD_; c2++)
                row[c2 + ((c2 >= 32) ? bp : 0)] = y[c2];
        }
    }
    __syncthreads();

    // ---- fused RoPE remix + coalesced stage-out
    // Thread (j = t&7, rslot = t>>3) computes out[4j..4j+3] AND out[4j+32..35]
    // of rows r = rslot + 16*i from ONE set of 8 y-reads (conflict-free banks).
    {
        const int j = t & 7;
        const int rslot = t >> 3;          // 0..15
        const int c0 = 8 * j;              // y columns 8j..8j+7 (never spans 32)
        const int off0 = c0 + ((j >= 4) ? bpad(rslot & 3) : 0);

        #pragma unroll
        for (int i = 0; i < 8; i++) {
            int r = rslot + 16 * i;        // s-group == i
            float4 cv = *(const float4*)&s_cos[i * NR_ + 4 * j];
            float4 sv = *(const float4*)&s_sin[i * NR_ + 4 * j];
            const float* row = &sm[r * PITCH + off0];
            float a0 = row[0], b0 = row[1];
            float a1 = row[2], b1 = row[3];
            float a2 = row[4], b2 = row[5];
            float a3 = row[6], b3 = row[7];
            float4 lo, hi;
            lo.x = a0 * cv.x - b0 * sv.x;  hi.x = a0 * sv.x + b0 * cv.x;
            lo.y = a1 * cv.y - b1 * sv.y;  hi.y = a1 * sv.y + b1 * cv.y;
            lo.z = a2 * cv.z - b2 * sv.z;  hi.z = a2 * sv.z + b2 * cv.z;
            lo.w = a3 * cv.w - b3 * sv.w;  hi.w = a3 * sv.w + b3 * cv.w;
            o4[r * 16 + j]     = lo;
            o4[r * 16 + 8 + j] = hi;
        }
    }
}

// ---------------------------------------------------------------------------
extern "C" void kernel_launch(void* const* d_in, const int* in_sizes, int n_in,
                              void* d_out, int out_size) {
    const float* x           = (const float*)d_in[0];
    const float* thetas      = (const float*)d_in[1];
    const float* r_pairs     = (const float*)d_in[2];
    const float* theta_scale = (const float*)d_in[3];
    // d_in[4] = n_rots_scale (unused by reference)
    const float* r_matrix    = (const float*)d_in[5];
    const float* inv_freq    = (const float*)d_in[6];
    float* out = (float*)d_out;

    rotary_fused_kernel<<<ROWS_ / RPB, RPB>>>(x, thetas, r_pairs, theta_scale,
                                              inv_freq, r_matrix, out);
}